// round 10
// baseline (speedup 1.0000x reference)
#include <cuda_runtime.h>
#include <cuda_fp16.h>
#include <cstdint>

#define NROWS  8192
#define DDIM   128
#define BM     128
#define NB     (NROWS / BM)              // 64
#define NPAIRS (NB * (NB + 1) / 2)       // 2080
#define GRID_MMA 296                     // 2 per SM, static contiguous ranges
#define MARGIN 0.3f

// ---------------- device scratch (no allocations allowed) ----------------
__device__ unsigned g_hp[NROWS];
__device__ unsigned g_hn[NROWS];
__device__ __align__(16) float2 g_meta[NROWS];        // {label bits, sqnorm}
__device__ __align__(16) __half g_X16[NROWS * DDIM];
__device__ unsigned g_done;

// ---------------- helpers ----------------
__device__ __forceinline__ uint32_t smem_u32(const void* p) {
    uint32_t a;
    asm("{ .reg .u64 t; cvta.to.shared.u64 t, %1; cvt.u32.u64 %0, t; }" : "=r"(a) : "l"(p));
    return a;
}
__device__ __forceinline__ void cp_async16(uint32_t s, const void* g) {
    asm volatile("cp.async.cg.shared.global [%0], [%1], 16;" :: "r"(s), "l"(g));
}
#define CP_COMMIT() asm volatile("cp.async.commit_group;" ::: "memory")
#define CP_WAIT0()  asm volatile("cp.async.wait_group 0;" ::: "memory")

__device__ __forceinline__ void ldsm_x4(uint32_t* d, uint32_t addr) {
    asm volatile("ldmatrix.sync.aligned.m8n8.x4.shared.b16 {%0,%1,%2,%3}, [%4];"
                 : "=r"(d[0]), "=r"(d[1]), "=r"(d[2]), "=r"(d[3]) : "r"(addr));
}
__device__ __forceinline__ void mma16816(float* c, const uint32_t* a, uint32_t b0, uint32_t b1) {
    asm volatile("mma.sync.aligned.m16n8k16.row.col.f32.f16.f16.f32 "
                 "{%0,%1,%2,%3}, {%4,%5,%6,%7}, {%8,%9}, {%0,%1,%2,%3};"
                 : "+f"(c[0]), "+f"(c[1]), "+f"(c[2]), "+f"(c[3])
                 : "r"(a[0]), "r"(a[1]), "r"(a[2]), "r"(a[3]), "r"(b0), "r"(b1));
}

// swizzled byte offset within a 128x128 fp16 tile: row r (256B rows), 16B chunk c16
#define SWZ(r, c) ((uint32_t)((r) * 256 + ((((c) ^ ((r) & 7))) * 16)))

// ---------------- smem layout (bytes): A + 2xB, fits 2 CTA/SM ----------------
#define SM_A    0
#define SM_B0   32768
#define SM_B1   65536
#define SM_MA   98304
#define SM_MB0  99328
#define SM_MB1  100352
#define SM_MINE 101376          // 512 u32: rowHP rowHN colHP colHN
#define SM_TOT  103424

// ---------------- prep: labels + norms + fp16 + init, 2 rows per warp (MLP=2) ----------------
__global__ __launch_bounds__(256) void prep_kernel(const float* __restrict__ X,
                                                   const int* __restrict__ lab32) {
    __shared__ int smode;
    const int tid = threadIdx.x, wid = tid >> 5, lane = tid & 31;
    if (tid == 0) {
        smode = 1;
        if (blockIdx.x == 0) g_done = 0u;
    }
    __syncthreads();
    // int64 labels (values < 2^31) => odd 32-bit words all zero. 64 samples.
    if (tid < 64 && lab32[2 * tid + 1] != 0) smode = 0;   // benign race: only writes 0
    __syncthreads();
    const int m64 = smode;

    const int row0 = blockIdx.x * 16 + wid * 2;
    float4 v0 = reinterpret_cast<const float4*>(X + row0 * DDIM)[lane];
    float4 v1 = reinterpret_cast<const float4*>(X + (row0 + 1) * DDIM)[lane];
    float s0 = fmaf(v0.w, v0.w, fmaf(v0.z, v0.z, fmaf(v0.y, v0.y, v0.x * v0.x)));
    float s1 = fmaf(v1.w, v1.w, fmaf(v1.z, v1.z, fmaf(v1.y, v1.y, v1.x * v1.x)));
    #pragma unroll
    for (int o = 16; o; o >>= 1) {
        s0 += __shfl_xor_sync(0xffffffffu, s0, o);
        s1 += __shfl_xor_sync(0xffffffffu, s1, o);
    }
    __half2* d0 = reinterpret_cast<__half2*>(g_X16 + row0 * DDIM) + lane * 2;
    __half2* d1 = reinterpret_cast<__half2*>(g_X16 + (row0 + 1) * DDIM) + lane * 2;
    d0[0] = __floats2half2_rn(v0.x, v0.y);
    d0[1] = __floats2half2_rn(v0.z, v0.w);
    d1[0] = __floats2half2_rn(v1.x, v1.y);
    d1[1] = __floats2half2_rn(v1.z, v1.w);
    if (lane == 0) {
        int la = m64 ? lab32[2 * row0] : lab32[row0];
        int lb = m64 ? lab32[2 * (row0 + 1)] : lab32[row0 + 1];
        float2 ma; ma.x = __int_as_float(la); ma.y = s0;
        float2 mb; mb.x = __int_as_float(lb); mb.y = s1;
        g_meta[row0] = ma;       g_meta[row0 + 1] = mb;
        g_hp[row0] = 0u;         g_hp[row0 + 1] = 0u;
        g_hn[row0] = 0x7f800000u; g_hn[row0 + 1] = 0x7f800000u;
    }
}

// ---------------- symmetric HMMA + dual mining; static ranges, B prefetch; inline finalize ----------------
__global__ __launch_bounds__(256, 2) void mma_kernel(float* __restrict__ out) {
    extern __shared__ char smem[];
    __shared__ int s_last;
    const uint32_t sb = smem_u32(smem);
    const int tid = threadIdx.x, wid = tid >> 5, lane = tid & 31;
    const int warpM = wid & 3, warpN = wid >> 2;     // 4 M-warps x 2 N-warps, warp tile 32x64

    // static contiguous pair range: base 7, first 8 CTAs get 8
    const int c = blockIdx.x;
    const int s0 = c * 7 + (c < 8 ? c : 8);
    const int n  = 7 + (c < 8 ? 1 : 0);
    int i = 0;
    while ((i + 1) * (129 - (i + 1)) / 2 <= s0) i++;
    int j = i + (s0 - i * (129 - i) / 2);

    // ldmatrix offsets (swizzle XOR term is lane&7 for every fragment)
    const int hi = lane >> 4, sw = lane & 7, rl = lane & 15;
    uint32_t aRel[2], bRel[4];
    #pragma unroll
    for (int mf = 0; mf < 2; mf++) aRel[mf] = sb + SM_A + (uint32_t)(warpM * 32 + mf * 16 + rl) * 256;
    #pragma unroll
    for (int bn = 0; bn < 4; bn++) bRel[bn] = (uint32_t)(warpN * 64 + bn * 16 + rl) * 256;

    unsigned* rowHP = reinterpret_cast<unsigned*>(smem + SM_MINE);
    unsigned* rowHN = rowHP + 128;
    unsigned* colHP = rowHP + 256;
    unsigned* colHN = rowHP + 384;

    // initial loads: A(i), B0(j), MA, MB0
    #pragma unroll
    for (int it = 0; it < 8; it++) {
        int lin = tid + it * 256;
        int r = lin >> 4, cc = lin & 15;
        uint32_t so = SWZ(r, cc);
        cp_async16(sb + SM_A + so, (const char*)(g_X16 + (i * BM + r) * DDIM) + cc * 16);
        cp_async16(sb + SM_B0 + so, (const char*)(g_X16 + (j * BM + r) * DDIM) + cc * 16);
    }
    if (tid < 64) {
        cp_async16(sb + SM_MA + tid * 16, (const char*)(g_meta + i * BM) + tid * 16);
        cp_async16(sb + SM_MB0 + tid * 16, (const char*)(g_meta + j * BM) + tid * 16);
    }
    CP_COMMIT();
    // init mining smem
    {
        unsigned iv = (tid & 128) ? 0x7f800000u : 0u;
        rowHP[tid] = iv;
        rowHP[tid + 256] = iv;
    }

    int buf = 0;
    for (int q = 0; q < n; q++) {
        CP_WAIT0();
        __syncthreads();

        const float2* mA = reinterpret_cast<const float2*>(smem + SM_MA);
        const float2* mB = reinterpret_cast<const float2*>(smem + (buf ? SM_MB1 : SM_MB0));
        const uint32_t bufB = sb + (buf ? SM_B1 : SM_B0);

        float sqa[4]; int labA[4];
        #pragma unroll
        for (int mf = 0; mf < 2; mf++) {
            float2 m0 = mA[warpM * 32 + mf * 16 + (lane >> 2)];
            float2 m1 = mA[warpM * 32 + mf * 16 + 8 + (lane >> 2)];
            sqa[mf * 2]     = m0.y; labA[mf * 2]     = __float_as_int(m0.x);
            sqa[mf * 2 + 1] = m1.y; labA[mf * 2 + 1] = __float_as_int(m1.x);
        }

        // next pair
        const bool have_next = (q + 1 < n);
        int ni = i, nj = j + 1;
        bool ich = false;
        if (nj == NB) { ni = i + 1; nj = ni; ich = true; }

        // prefetch next B + MB into the other buffer (safe during GEMM on buf)
        if (have_next) {
            const uint32_t nBo = sb + (buf ? SM_B0 : SM_B1);
            #pragma unroll
            for (int it = 0; it < 8; it++) {
                int lin = tid + it * 256;
                int r = lin >> 4, cc = lin & 15;
                cp_async16(nBo + SWZ(r, cc), (const char*)(g_X16 + (nj * BM + r) * DDIM) + cc * 16);
            }
            if (tid < 64)
                cp_async16(sb + (buf ? SM_MB0 : SM_MB1) + tid * 16,
                           (const char*)(g_meta + nj * BM) + tid * 16);
            CP_COMMIT();
        }

        // ---- GEMM 128x128x128 ----
        float acc[2][8][4];
        #pragma unroll
        for (int mf = 0; mf < 2; mf++)
            #pragma unroll
            for (int nf = 0; nf < 8; nf++)
                #pragma unroll
                for (int e = 0; e < 4; e++) acc[mf][nf][e] = 0.f;

        #pragma unroll
        for (int kc = 0; kc < 8; kc++) {
            const uint32_t cx = (uint32_t)(((2 * kc + hi) ^ sw) * 16);
            uint32_t a[2][4], b[4][4];
            #pragma unroll
            for (int mf = 0; mf < 2; mf++) ldsm_x4(a[mf], aRel[mf] + cx);
            #pragma unroll
            for (int bn = 0; bn < 4; bn++) ldsm_x4(b[bn], bufB + bRel[bn] + cx);
            #pragma unroll
            for (int mf = 0; mf < 2; mf++) {
                #pragma unroll
                for (int bn = 0; bn < 4; bn++) {
                    mma16816(acc[mf][bn * 2],     a[mf], b[bn][0], b[bn][2]);
                    mma16816(acc[mf][bn * 2 + 1], a[mf], b[bn][1], b[bn][3]);
                }
            }
        }

        // ---- epilogue: dual mining, no per-distance clamp ----
        float hp[4], hn[4];
        #pragma unroll
        for (int e = 0; e < 4; e++) { hp[e] = 0.f; hn[e] = __int_as_float(0x7f800000); }

        #pragma unroll
        for (int nf = 0; nf < 8; nf++) {
            const int cb = warpN * 64 + nf * 8 + (lane & 3) * 2;
            const float2 mv0 = mB[cb], mv1 = mB[cb + 1];
            const int lb0 = __float_as_int(mv0.x), lb1 = __float_as_int(mv1.x);
            float cp0 = 0.f, cp1 = 0.f;
            float cn0 = __int_as_float(0x7f800000), cn1 = cn0;
            #pragma unroll
            for (int mf = 0; mf < 2; mf++) {
                const int rlo = mf * 2, rhi = mf * 2 + 1;
                float d00 = fmaf(-2.f, acc[mf][nf][0], sqa[rlo] + mv0.y);
                float d01 = fmaf(-2.f, acc[mf][nf][1], sqa[rlo] + mv1.y);
                float d10 = fmaf(-2.f, acc[mf][nf][2], sqa[rhi] + mv0.y);
                float d11 = fmaf(-2.f, acc[mf][nf][3], sqa[rhi] + mv1.y);
                if (lb0 == labA[rlo]) { hp[rlo] = fmaxf(hp[rlo], d00); cp0 = fmaxf(cp0, d00); }
                else                  { hn[rlo] = fminf(hn[rlo], d00); cn0 = fminf(cn0, d00); }
                if (lb1 == labA[rlo]) { hp[rlo] = fmaxf(hp[rlo], d01); cp1 = fmaxf(cp1, d01); }
                else                  { hn[rlo] = fminf(hn[rlo], d01); cn1 = fminf(cn1, d01); }
                if (lb0 == labA[rhi]) { hp[rhi] = fmaxf(hp[rhi], d10); cp0 = fmaxf(cp0, d10); }
                else                  { hn[rhi] = fminf(hn[rhi], d10); cn0 = fminf(cn0, d10); }
                if (lb1 == labA[rhi]) { hp[rhi] = fmaxf(hp[rhi], d11); cp1 = fmaxf(cp1, d11); }
                else                  { hn[rhi] = fminf(hn[rhi], d11); cn1 = fminf(cn1, d11); }
            }
            #pragma unroll
            for (int o = 4; o <= 16; o <<= 1) {
                cp0 = fmaxf(cp0, __shfl_xor_sync(0xffffffffu, cp0, o));
                cp1 = fmaxf(cp1, __shfl_xor_sync(0xffffffffu, cp1, o));
                cn0 = fminf(cn0, __shfl_xor_sync(0xffffffffu, cn0, o));
                cn1 = fminf(cn1, __shfl_xor_sync(0xffffffffu, cn1, o));
            }
            if (lane < 4) {
                const int cc = warpN * 64 + nf * 8 + lane * 2;
                atomicMax(&colHP[cc],     __float_as_uint(cp0));
                atomicMin(&colHN[cc],     __float_as_uint(cn0));
                atomicMax(&colHP[cc + 1], __float_as_uint(cp1));
                atomicMin(&colHN[cc + 1], __float_as_uint(cn1));
            }
        }
        #pragma unroll
        for (int e = 0; e < 4; e++) {
            hp[e] = fmaxf(hp[e], __shfl_xor_sync(0xffffffffu, hp[e], 1));
            hp[e] = fmaxf(hp[e], __shfl_xor_sync(0xffffffffu, hp[e], 2));
            hn[e] = fminf(hn[e], __shfl_xor_sync(0xffffffffu, hn[e], 1));
            hn[e] = fminf(hn[e], __shfl_xor_sync(0xffffffffu, hn[e], 2));
        }
        if ((lane & 3) == 0) {
            #pragma unroll
            for (int e = 0; e < 4; e++) {
                int r = warpM * 32 + (e >> 1) * 16 + (e & 1) * 8 + (lane >> 2);
                atomicMax(&rowHP[r], __float_as_uint(hp[e]));
                atomicMin(&rowHN[r], __float_as_uint(hn[e]));
            }
        }
        __syncthreads();   // all mine atomics done; all GEMM/meta reads done

        // A reload on i-change (barrier-ordered vs all A/MA readers)
        if (have_next && ich) {
            #pragma unroll
            for (int it = 0; it < 8; it++) {
                int lin = tid + it * 256;
                int r = lin >> 4, cc = lin & 15;
                cp_async16(sb + SM_A + SWZ(r, cc), (const char*)(g_X16 + (ni * BM + r) * DDIM) + cc * 16);
            }
            if (tid < 64)
                cp_async16(sb + SM_MA + tid * 16, (const char*)(g_meta + ni * BM) + tid * 16);
            CP_COMMIT();
        }

        // global merge
        if (tid < 128) {
            atomicMax(&g_hp[i * BM + tid], rowHP[tid]);
            atomicMin(&g_hn[i * BM + tid], rowHN[tid]);
            atomicMax(&g_hp[j * BM + tid], colHP[tid]);
            atomicMin(&g_hn[j * BM + tid], colHN[tid]);
        }
        __syncthreads();
        // reset mine for next pair (ordered before next epilogue by loop-top sync)
        {
            unsigned iv = (tid & 128) ? 0x7f800000u : 0u;
            rowHP[tid] = iv;
            rowHP[tid + 256] = iv;
        }
        i = ni; j = nj; buf ^= 1;
    }

    // ---- inline finalize: last CTA computes the mean ----
    __threadfence();
    __syncthreads();
    if (tid == 0) s_last = (atomicAdd(&g_done, 1u) == GRID_MMA - 1) ? 1 : 0;
    __syncthreads();
    if (s_last) {
        float s = 0.f;
        #pragma unroll 4
        for (int r = tid; r < NROWS; r += 256) {
            float hpv = sqrtf(__uint_as_float(__ldcg(&g_hp[r])));
            float hnv = sqrtf(__uint_as_float(__ldcg(&g_hn[r])));     // +inf -> loss 0
            s += fmaxf(hpv - hnv + MARGIN, 0.f);
        }
        #pragma unroll
        for (int o = 16; o; o >>= 1) s += __shfl_xor_sync(0xffffffffu, s, o);
        float* red = reinterpret_cast<float*>(smem);   // smem free now
        if (lane == 0) red[wid] = s;
        __syncthreads();
        if (tid == 0) {
            float t = 0.f;
            #pragma unroll
            for (int w = 0; w < 8; w++) t += red[w];
            out[0] = t * (1.0f / (float)NROWS);
        }
    }
}

extern "C" void kernel_launch(void* const* d_in, const int* in_sizes, int n_in,
                              void* d_out, int out_size) {
    const float* X   = (const float*)d_in[0];
    const int* lab32 = (const int*)d_in[1];
    float* out = (float*)d_out;

    cudaFuncSetAttribute(mma_kernel, cudaFuncAttributeMaxDynamicSharedMemorySize, SM_TOT);

    prep_kernel<<<NROWS / 16, 256>>>(X, lab32);
    mma_kernel<<<GRID_MMA, 256, SM_TOT>>>(out);
}

// round 11
// speedup vs baseline: 1.2853x; 1.2853x over previous
#include <cuda_runtime.h>
#include <cuda_fp16.h>
#include <cstdint>

#define NROWS  8192
#define DDIM   128
#define BM     128
#define NB     (NROWS / BM)              // 64
#define NPAIRS (NB * (NB + 1) / 2)       // 2080
#define GRID_MMA 296                     // 2 per SM, persistent dynamic
#define MARGIN 0.3f

// ---------------- device scratch (no allocations allowed) ----------------
__device__ unsigned g_hp[NROWS];
__device__ unsigned g_hn[NROWS];
__device__ __align__(16) float2 g_meta[NROWS];        // {label bits, sqnorm}
__device__ __align__(16) __half g_X16[NROWS * DDIM];
__device__ unsigned long long g_isum;
__device__ unsigned g_done;
__device__ int g_work;

// ---------------- helpers ----------------
__device__ __forceinline__ uint32_t smem_u32(const void* p) {
    uint32_t a;
    asm("{ .reg .u64 t; cvta.to.shared.u64 t, %1; cvt.u32.u64 %0, t; }" : "=r"(a) : "l"(p));
    return a;
}
__device__ __forceinline__ void cp_async16(uint32_t s, const void* g) {
    asm volatile("cp.async.cg.shared.global [%0], [%1], 16;" :: "r"(s), "l"(g));
}
#define CP_COMMIT() asm volatile("cp.async.commit_group;" ::: "memory")
#define CP_WAIT0()  asm volatile("cp.async.wait_group 0;" ::: "memory")

__device__ __forceinline__ void ldsm_x4(uint32_t* d, uint32_t addr) {
    asm volatile("ldmatrix.sync.aligned.m8n8.x4.shared.b16 {%0,%1,%2,%3}, [%4];"
                 : "=r"(d[0]), "=r"(d[1]), "=r"(d[2]), "=r"(d[3]) : "r"(addr));
}
__device__ __forceinline__ void mma16816(float* c, const uint32_t* a, uint32_t b0, uint32_t b1) {
    asm volatile("mma.sync.aligned.m16n8k16.row.col.f32.f16.f16.f32 "
                 "{%0,%1,%2,%3}, {%4,%5,%6,%7}, {%8,%9}, {%0,%1,%2,%3};"
                 : "+f"(c[0]), "+f"(c[1]), "+f"(c[2]), "+f"(c[3])
                 : "r"(a[0]), "r"(a[1]), "r"(a[2]), "r"(a[3]), "r"(b0), "r"(b1));
}

// swizzled byte offset within a 128x128 fp16 tile: row r (256B rows), 16B chunk c16
#define SWZ(r, c) ((uint32_t)((r) * 256 + ((((c) ^ ((r) & 7))) * 16)))

// ---------------- smem layout (bytes): single A/B, double meta-B; 2 CTA/SM ----------------
#define SM_A    0
#define SM_B    32768
#define SM_MA   65536
#define SM_MB0  66560
#define SM_MB1  67584
#define SM_MINE 68608           // 512 u32: rowHP rowHN colHP colHN
#define SM_SP   70656
#define SM_TOT  70672

// ---------------- prep: labels + norms + fp16 + init, 2 rows per warp ----------------
__global__ __launch_bounds__(256) void prep_kernel(const float* __restrict__ X,
                                                   const int* __restrict__ lab32) {
    __shared__ int smode;
    const int tid = threadIdx.x, wid = tid >> 5, lane = tid & 31;
    if (tid == 0) {
        smode = 1;
        if (blockIdx.x == 0) { g_isum = 0ull; g_done = 0u; g_work = 0; }
    }
    __syncthreads();
    // int64 labels (values < 2^31) => odd 32-bit words all zero. 64 samples.
    if (tid < 64 && lab32[2 * tid + 1] != 0) smode = 0;   // benign race: only writes 0
    __syncthreads();
    const int m64 = smode;

    const int row0 = blockIdx.x * 16 + wid * 2;
    float4 v0 = reinterpret_cast<const float4*>(X + row0 * DDIM)[lane];
    float4 v1 = reinterpret_cast<const float4*>(X + (row0 + 1) * DDIM)[lane];
    float s0 = fmaf(v0.w, v0.w, fmaf(v0.z, v0.z, fmaf(v0.y, v0.y, v0.x * v0.x)));
    float s1 = fmaf(v1.w, v1.w, fmaf(v1.z, v1.z, fmaf(v1.y, v1.y, v1.x * v1.x)));
    #pragma unroll
    for (int o = 16; o; o >>= 1) {
        s0 += __shfl_xor_sync(0xffffffffu, s0, o);
        s1 += __shfl_xor_sync(0xffffffffu, s1, o);
    }
    __half2* d0 = reinterpret_cast<__half2*>(g_X16 + row0 * DDIM) + lane * 2;
    __half2* d1 = reinterpret_cast<__half2*>(g_X16 + (row0 + 1) * DDIM) + lane * 2;
    d0[0] = __floats2half2_rn(v0.x, v0.y);
    d0[1] = __floats2half2_rn(v0.z, v0.w);
    d1[0] = __floats2half2_rn(v1.x, v1.y);
    d1[1] = __floats2half2_rn(v1.z, v1.w);
    if (lane == 0) {
        int la = m64 ? lab32[2 * row0] : lab32[row0];
        int lb = m64 ? lab32[2 * (row0 + 1)] : lab32[row0 + 1];
        float2 ma; ma.x = __int_as_float(la); ma.y = s0;
        float2 mb; mb.x = __int_as_float(lb); mb.y = s1;
        g_meta[row0] = ma;        g_meta[row0 + 1] = mb;
        g_hp[row0] = 0u;          g_hp[row0 + 1] = 0u;
        g_hn[row0] = 0x7f800000u; g_hn[row0 + 1] = 0x7f800000u;
    }
}

__device__ __forceinline__ void decode_pair(int p, int& i, int& j) {
    int t = (int)((129.0f - sqrtf(16641.0f - 8.0f * (float)p)) * 0.5f);
    while ((t + 1) * (129 - (t + 1)) / 2 <= p) t++;
    while (t * (129 - t) / 2 > p) t--;
    i = t;
    j = t + (p - t * (129 - t) / 2);
}

__device__ __forceinline__ void issue_pair_loads(uint32_t sb, int tid, int i, int j, int mbuf) {
    #pragma unroll
    for (int it = 0; it < 8; it++) {
        int lin = tid + it * 256;
        int r = lin >> 4, cc = lin & 15;
        uint32_t so = SWZ(r, cc);
        cp_async16(sb + SM_A + so, (const char*)(g_X16 + (i * BM + r) * DDIM) + cc * 16);
        cp_async16(sb + SM_B + so, (const char*)(g_X16 + (j * BM + r) * DDIM) + cc * 16);
    }
    if (tid < 64) {
        cp_async16(sb + SM_MA + tid * 16, (const char*)(g_meta + i * BM) + tid * 16);
        cp_async16(sb + (mbuf ? SM_MB1 : SM_MB0) + tid * 16, (const char*)(g_meta + j * BM) + tid * 16);
    }
    CP_COMMIT();
}

// ---------------- persistent dynamic symmetric HMMA + dual mining, loads under epilogue ----------------
__global__ __launch_bounds__(256, 2) void mma_kernel() {
    extern __shared__ char smem[];
    const uint32_t sb = smem_u32(smem);
    const int tid = threadIdx.x, wid = tid >> 5, lane = tid & 31;
    const int warpM = wid & 3, warpN = wid >> 2;     // 4 M-warps x 2 N-warps, warp tile 32x64
    int* s_p = reinterpret_cast<int*>(smem + SM_SP);

    // ldmatrix offsets (swizzle XOR term is lane&7 for every fragment)
    const int hi = lane >> 4, sw = lane & 7, rl = lane & 15;
    uint32_t aRel[2], bRel[4];
    #pragma unroll
    for (int mf = 0; mf < 2; mf++) aRel[mf] = sb + SM_A + (uint32_t)(warpM * 32 + mf * 16 + rl) * 256;
    #pragma unroll
    for (int bn = 0; bn < 4; bn++) bRel[bn] = sb + SM_B + (uint32_t)(warpN * 64 + bn * 16 + rl) * 256;

    unsigned* rowHP = reinterpret_cast<unsigned*>(smem + SM_MINE);
    unsigned* rowHN = rowHP + 128;
    unsigned* colHP = rowHP + 256;
    unsigned* colHN = rowHP + 384;

    // init mining smem
    {
        unsigned iv = (tid & 128) ? 0x7f800000u : 0u;
        rowHP[tid] = iv;
        rowHP[tid + 256] = iv;
    }
    // first claim + first loads
    if (tid == 0) *s_p = atomicAdd(&g_work, 1);
    __syncthreads();
    int p = *s_p, i = 0, j = 0, mbuf = 0;
    if (p < NPAIRS) {
        decode_pair(p, i, j);
        issue_pair_loads(sb, tid, i, j, 0);
    }

    while (p < NPAIRS) {
        // claim the NEXT pair now (ATOMG latency hidden under wait+GEMM)
        if (tid == 0) *s_p = atomicAdd(&g_work, 1);
        CP_WAIT0();
        __syncthreads();

        const float2* mA = reinterpret_cast<const float2*>(smem + SM_MA);
        const float2* mB = reinterpret_cast<const float2*>(smem + (mbuf ? SM_MB1 : SM_MB0));

        float sqa[4]; int labA[4];
        #pragma unroll
        for (int mf = 0; mf < 2; mf++) {
            float2 m0 = mA[warpM * 32 + mf * 16 + (lane >> 2)];
            float2 m1 = mA[warpM * 32 + mf * 16 + 8 + (lane >> 2)];
            sqa[mf * 2]     = m0.y; labA[mf * 2]     = __float_as_int(m0.x);
            sqa[mf * 2 + 1] = m1.y; labA[mf * 2 + 1] = __float_as_int(m1.x);
        }

        // ---- GEMM 128x128x128 (reads A,B smem) ----
        float acc[2][8][4];
        #pragma unroll
        for (int mf = 0; mf < 2; mf++)
            #pragma unroll
            for (int nf = 0; nf < 8; nf++)
                #pragma unroll
                for (int e = 0; e < 4; e++) acc[mf][nf][e] = 0.f;

        #pragma unroll
        for (int kc = 0; kc < 8; kc++) {
            const uint32_t cx = (uint32_t)(((2 * kc + hi) ^ sw) * 16);
            uint32_t a[2][4], b[4][4];
            #pragma unroll
            for (int mf = 0; mf < 2; mf++) ldsm_x4(a[mf], aRel[mf] + cx);
            #pragma unroll
            for (int bn = 0; bn < 4; bn++) ldsm_x4(b[bn], bRel[bn] + cx);
            #pragma unroll
            for (int mf = 0; mf < 2; mf++) {
                #pragma unroll
                for (int bn = 0; bn < 4; bn++) {
                    mma16816(acc[mf][bn * 2],     a[mf], b[bn][0], b[bn][2]);
                    mma16816(acc[mf][bn * 2 + 1], a[mf], b[bn][1], b[bn][3]);
                }
            }
        }

        __syncthreads();   // all A/B smem reads complete; s_p visible

        // issue next pair's loads NOW — they fly under the epilogue
        const int pn = *s_p;
        int ni = 0, nj = 0;
        if (pn < NPAIRS) {
            decode_pair(pn, ni, nj);
            issue_pair_loads(sb, tid, ni, nj, mbuf ^ 1);
        }

        // ---- epilogue: dual mining (no per-distance clamp) ----
        float hp[4], hn[4];
        #pragma unroll
        for (int e = 0; e < 4; e++) { hp[e] = 0.f; hn[e] = __int_as_float(0x7f800000); }

        #pragma unroll
        for (int nf = 0; nf < 8; nf++) {
            const int cb = warpN * 64 + nf * 8 + (lane & 3) * 2;
            const float2 mv0 = mB[cb], mv1 = mB[cb + 1];
            const int lb0 = __float_as_int(mv0.x), lb1 = __float_as_int(mv1.x);
            float cp0 = 0.f, cp1 = 0.f;
            float cn0 = __int_as_float(0x7f800000), cn1 = cn0;
            #pragma unroll
            for (int mf = 0; mf < 2; mf++) {
                const int rlo = mf * 2, rhi = mf * 2 + 1;
                float d00 = fmaf(-2.f, acc[mf][nf][0], sqa[rlo] + mv0.y);
                float d01 = fmaf(-2.f, acc[mf][nf][1], sqa[rlo] + mv1.y);
                float d10 = fmaf(-2.f, acc[mf][nf][2], sqa[rhi] + mv0.y);
                float d11 = fmaf(-2.f, acc[mf][nf][3], sqa[rhi] + mv1.y);
                if (lb0 == labA[rlo]) { hp[rlo] = fmaxf(hp[rlo], d00); cp0 = fmaxf(cp0, d00); }
                else                  { hn[rlo] = fminf(hn[rlo], d00); cn0 = fminf(cn0, d00); }
                if (lb1 == labA[rlo]) { hp[rlo] = fmaxf(hp[rlo], d01); cp1 = fmaxf(cp1, d01); }
                else                  { hn[rlo] = fminf(hn[rlo], d01); cn1 = fminf(cn1, d01); }
                if (lb0 == labA[rhi]) { hp[rhi] = fmaxf(hp[rhi], d10); cp0 = fmaxf(cp0, d10); }
                else                  { hn[rhi] = fminf(hn[rhi], d10); cn0 = fminf(cn0, d10); }
                if (lb1 == labA[rhi]) { hp[rhi] = fmaxf(hp[rhi], d11); cp1 = fmaxf(cp1, d11); }
                else                  { hn[rhi] = fminf(hn[rhi], d11); cn1 = fminf(cn1, d11); }
            }
            #pragma unroll
            for (int o = 4; o <= 16; o <<= 1) {
                cp0 = fmaxf(cp0, __shfl_xor_sync(0xffffffffu, cp0, o));
                cp1 = fmaxf(cp1, __shfl_xor_sync(0xffffffffu, cp1, o));
                cn0 = fminf(cn0, __shfl_xor_sync(0xffffffffu, cn0, o));
                cn1 = fminf(cn1, __shfl_xor_sync(0xffffffffu, cn1, o));
            }
            if (lane < 4) {
                const int cc = warpN * 64 + nf * 8 + lane * 2;
                atomicMax(&colHP[cc],     __float_as_uint(cp0));
                atomicMin(&colHN[cc],     __float_as_uint(cn0));
                atomicMax(&colHP[cc + 1], __float_as_uint(cp1));
                atomicMin(&colHN[cc + 1], __float_as_uint(cn1));
            }
        }
        #pragma unroll
        for (int e = 0; e < 4; e++) {
            hp[e] = fmaxf(hp[e], __shfl_xor_sync(0xffffffffu, hp[e], 1));
            hp[e] = fmaxf(hp[e], __shfl_xor_sync(0xffffffffu, hp[e], 2));
            hn[e] = fminf(hn[e], __shfl_xor_sync(0xffffffffu, hn[e], 1));
            hn[e] = fminf(hn[e], __shfl_xor_sync(0xffffffffu, hn[e], 2));
        }
        if ((lane & 3) == 0) {
            #pragma unroll
            for (int e = 0; e < 4; e++) {
                int r = warpM * 32 + (e >> 1) * 16 + (e & 1) * 8 + (lane >> 2);
                atomicMax(&rowHP[r], __float_as_uint(hp[e]));
                atomicMin(&rowHN[r], __float_as_uint(hn[e]));
            }
        }
        __syncthreads();   // all mine atomics done

        // global merge (REDG: results unused)
        if (tid < 128) {
            atomicMax(&g_hp[i * BM + tid], rowHP[tid]);
            atomicMin(&g_hn[i * BM + tid], rowHN[tid]);
            atomicMax(&g_hp[j * BM + tid], colHP[tid]);
            atomicMin(&g_hn[j * BM + tid], colHN[tid]);
        }
        __syncthreads();
        // reset mine for next pair (ordered vs next epilogue by loop-top barrier)
        {
            unsigned iv = (tid & 128) ? 0x7f800000u : 0u;
            rowHP[tid] = iv;
            rowHP[tid + 256] = iv;
        }
        p = pn; i = ni; j = nj; mbuf ^= 1;
    }
}

// ---------------- finalize: 64 blocks, deterministic fixed-point accumulation ----------------
__global__ void finalize_kernel(float* __restrict__ out) {
    __shared__ float red[4];
    const int tid = threadIdx.x, wid = tid >> 5, lane = tid & 31;
    const int r = blockIdx.x * 128 + tid;
    float hp = sqrtf(__uint_as_float(g_hp[r]));
    float hn = sqrtf(__uint_as_float(g_hn[r]));    // +inf -> loss 0
    float s = fmaxf(hp - hn + MARGIN, 0.f);
    #pragma unroll
    for (int o = 16; o; o >>= 1) s += __shfl_xor_sync(0xffffffffu, s, o);
    if (lane == 0) red[wid] = s;
    __syncthreads();
    if (tid == 0) {
        float bs = red[0] + red[1] + red[2] + red[3];
        unsigned long long qv = (unsigned long long)__float2ll_rn(bs * 16777216.0f);
        atomicAdd(&g_isum, qv);
        __threadfence();
        unsigned done = atomicAdd(&g_done, 1u);
        if (done == 63u) {
            unsigned long long v = atomicAdd(&g_isum, 0ull);
            out[0] = (float)((double)v * (1.0 / (16777216.0 * 8192.0)));
        }
    }
}

extern "C" void kernel_launch(void* const* d_in, const int* in_sizes, int n_in,
                              void* d_out, int out_size) {
    const float* X   = (const float*)d_in[0];
    const int* lab32 = (const int*)d_in[1];
    float* out = (float*)d_out;

    cudaFuncSetAttribute(mma_kernel, cudaFuncAttributeMaxDynamicSharedMemorySize, SM_TOT);

    prep_kernel<<<NROWS / 16, 256>>>(X, lab32);
    mma_kernel<<<GRID_MMA, 256, SM_TOT>>>();
    finalize_kernel<<<64, 128>>>(out);
}

// round 13
// speedup vs baseline: 1.2979x; 1.0098x over previous
#include <cuda_runtime.h>
#include <cuda_fp16.h>
#include <cstdint>

#define NROWS  8192
#define DDIM   128
#define BM     128
#define NB     (NROWS / BM)              // 64
#define NPAIRS (NB * (NB + 1) / 2)       // 2080
#define GRID_MMA 296                     // 2 per SM, persistent dynamic
#define MARGIN 0.3f

// ---------------- device scratch (no allocations allowed) ----------------
__device__ unsigned g_hp[NROWS];
__device__ unsigned g_hn[NROWS];
__device__ __align__(16) float2 g_meta[NROWS];        // {label bits, sqnorm}
__device__ __align__(16) __half g_X16[NROWS * DDIM];
__device__ unsigned long long g_isum;
__device__ unsigned g_done;
__device__ int g_work;

// ---------------- helpers ----------------
__device__ __forceinline__ uint32_t smem_u32(const void* p) {
    uint32_t a;
    asm("{ .reg .u64 t; cvta.to.shared.u64 t, %1; cvt.u32.u64 %0, t; }" : "=r"(a) : "l"(p));
    return a;
}
__device__ __forceinline__ void cp_async16(uint32_t s, const void* g) {
    asm volatile("cp.async.cg.shared.global [%0], [%1], 16;" :: "r"(s), "l"(g));
}
#define CP_COMMIT() asm volatile("cp.async.commit_group;" ::: "memory")
#define CP_WAIT0()  asm volatile("cp.async.wait_group 0;" ::: "memory")

__device__ __forceinline__ void ldsm_x4(uint32_t* d, uint32_t addr) {
    asm volatile("ldmatrix.sync.aligned.m8n8.x4.shared.b16 {%0,%1,%2,%3}, [%4];"
                 : "=r"(d[0]), "=r"(d[1]), "=r"(d[2]), "=r"(d[3]) : "r"(addr));
}
__device__ __forceinline__ void mma16816(float* c, const uint32_t* a, uint32_t b0, uint32_t b1) {
    asm volatile("mma.sync.aligned.m16n8k16.row.col.f32.f16.f16.f32 "
                 "{%0,%1,%2,%3}, {%4,%5,%6,%7}, {%8,%9}, {%0,%1,%2,%3};"
                 : "+f"(c[0]), "+f"(c[1]), "+f"(c[2]), "+f"(c[3])
                 : "r"(a[0]), "r"(a[1]), "r"(a[2]), "r"(a[3]), "r"(b0), "r"(b1));
}

// swizzled byte offset within a 128x128 fp16 tile: row r (256B rows), 16B chunk c16
#define SWZ(r, c) ((uint32_t)((r) * 256 + ((((c) ^ ((r) & 7))) * 16)))

// ---------------- smem layout (bytes): single A/B, double meta-B; 2 CTA/SM ----------------
#define SM_A    0
#define SM_B    32768
#define SM_MA   65536
#define SM_MB0  66560
#define SM_MB1  67584
#define SM_SP   68608
#define SM_TOT  68624

// ---------------- prep: labels + norms + fp16 + init, 4 rows per warp (MLP=4) ----------------
__global__ __launch_bounds__(256) void prep_kernel(const float* __restrict__ X,
                                                   const int* __restrict__ lab32) {
    __shared__ int smode;
    const int tid = threadIdx.x, wid = tid >> 5, lane = tid & 31;
    if (tid == 0) {
        smode = 1;
        if (blockIdx.x == 0) { g_isum = 0ull; g_done = 0u; g_work = 0; }
    }
    __syncthreads();
    // int64 labels (values < 2^31) => odd 32-bit words all zero. 64 samples.
    if (tid < 64 && lab32[2 * tid + 1] != 0) smode = 0;   // benign race: only writes 0
    __syncthreads();
    const int m64 = smode;

    const int row0 = blockIdx.x * 32 + wid * 4;
    float4 v[4];
    #pragma unroll
    for (int r = 0; r < 4; r++) v[r] = reinterpret_cast<const float4*>(X + (row0 + r) * DDIM)[lane];
    float s[4];
    #pragma unroll
    for (int r = 0; r < 4; r++)
        s[r] = fmaf(v[r].w, v[r].w, fmaf(v[r].z, v[r].z, fmaf(v[r].y, v[r].y, v[r].x * v[r].x)));
    #pragma unroll
    for (int o = 16; o; o >>= 1) {
        #pragma unroll
        for (int r = 0; r < 4; r++) s[r] += __shfl_xor_sync(0xffffffffu, s[r], o);
    }
    #pragma unroll
    for (int r = 0; r < 4; r++) {
        __half2* d = reinterpret_cast<__half2*>(g_X16 + (row0 + r) * DDIM) + lane * 2;
        d[0] = __floats2half2_rn(v[r].x, v[r].y);
        d[1] = __floats2half2_rn(v[r].z, v[r].w);
    }
    if (lane < 4) {
        const int row = row0 + lane;
        int lab = m64 ? lab32[2 * row] : lab32[row];
        // s[r] is uniform across lanes post-butterfly; lane r uses its own s[r]
        // (static 4-way select — NOT a shuffle; the r12 shfl read lane 0's s[0] for all rows)
        float sv = (lane == 0) ? s[0] : (lane == 1) ? s[1] : (lane == 2) ? s[2] : s[3];
        float2 m; m.x = __int_as_float(lab); m.y = sv;
        g_meta[row] = m;
        g_hp[row] = 0u;
        g_hn[row] = 0x7f800000u;
    }
}

__device__ __forceinline__ void decode_pair(int p, int& i, int& j) {
    int t = (int)((129.0f - sqrtf(16641.0f - 8.0f * (float)p)) * 0.5f);
    while ((t + 1) * (129 - (t + 1)) / 2 <= p) t++;
    while (t * (129 - t) / 2 > p) t--;
    i = t;
    j = t + (p - t * (129 - t) / 2);
}

__device__ __forceinline__ void issue_pair_loads(uint32_t sb, int tid, int i, int j, int mbuf) {
    #pragma unroll
    for (int it = 0; it < 8; it++) {
        int lin = tid + it * 256;
        int r = lin >> 4, cc = lin & 15;
        uint32_t so = SWZ(r, cc);
        cp_async16(sb + SM_A + so, (const char*)(g_X16 + (i * BM + r) * DDIM) + cc * 16);
        cp_async16(sb + SM_B + so, (const char*)(g_X16 + (j * BM + r) * DDIM) + cc * 16);
    }
    if (tid < 64) {
        cp_async16(sb + SM_MA + tid * 16, (const char*)(g_meta + i * BM) + tid * 16);
        cp_async16(sb + (mbuf ? SM_MB1 : SM_MB0) + tid * 16, (const char*)(g_meta + j * BM) + tid * 16);
    }
    CP_COMMIT();
}

// ---------------- persistent dynamic symmetric HMMA + dual mining (direct REDG) ----------------
__global__ __launch_bounds__(256, 2) void mma_kernel() {
    extern __shared__ char smem[];
    const uint32_t sb = smem_u32(smem);
    const int tid = threadIdx.x, wid = tid >> 5, lane = tid & 31;
    const int warpM = wid & 3, warpN = wid >> 2;     // 4 M-warps x 2 N-warps, warp tile 32x64
    int* s_p = reinterpret_cast<int*>(smem + SM_SP);

    // ldmatrix offsets (swizzle XOR term is lane&7 for every fragment)
    const int hi = lane >> 4, sw = lane & 7, rl = lane & 15;
    uint32_t aRel[2], bRel[4];
    #pragma unroll
    for (int mf = 0; mf < 2; mf++) aRel[mf] = sb + SM_A + (uint32_t)(warpM * 32 + mf * 16 + rl) * 256;
    #pragma unroll
    for (int bn = 0; bn < 4; bn++) bRel[bn] = sb + SM_B + (uint32_t)(warpN * 64 + bn * 16 + rl) * 256;

    // first claim + first loads
    if (tid == 0) *s_p = atomicAdd(&g_work, 1);
    __syncthreads();
    int p = *s_p, i = 0, j = 0, mbuf = 0;
    if (p < NPAIRS) {
        decode_pair(p, i, j);
        issue_pair_loads(sb, tid, i, j, 0);
    }

    while (p < NPAIRS) {
        // claim the NEXT pair now (ATOMG latency hidden under wait+GEMM)
        if (tid == 0) *s_p = atomicAdd(&g_work, 1);
        CP_WAIT0();
        __syncthreads();

        const float2* mA = reinterpret_cast<const float2*>(smem + SM_MA);
        const float2* mB = reinterpret_cast<const float2*>(smem + (mbuf ? SM_MB1 : SM_MB0));

        float sqa[4]; int labA[4];
        #pragma unroll
        for (int mf = 0; mf < 2; mf++) {
            float2 m0 = mA[warpM * 32 + mf * 16 + (lane >> 2)];
            float2 m1 = mA[warpM * 32 + mf * 16 + 8 + (lane >> 2)];
            sqa[mf * 2]     = m0.y; labA[mf * 2]     = __float_as_int(m0.x);
            sqa[mf * 2 + 1] = m1.y; labA[mf * 2 + 1] = __float_as_int(m1.x);
        }

        // ---- GEMM 128x128x128 (reads A,B smem) ----
        float acc[2][8][4];
        #pragma unroll
        for (int mf = 0; mf < 2; mf++)
            #pragma unroll
            for (int nf = 0; nf < 8; nf++)
                #pragma unroll
                for (int e = 0; e < 4; e++) acc[mf][nf][e] = 0.f;

        #pragma unroll
        for (int kc = 0; kc < 8; kc++) {
            const uint32_t cx = (uint32_t)(((2 * kc + hi) ^ sw) * 16);
            uint32_t a[2][4], b[4][4];
            #pragma unroll
            for (int mf = 0; mf < 2; mf++) ldsm_x4(a[mf], aRel[mf] + cx);
            #pragma unroll
            for (int bn = 0; bn < 4; bn++) ldsm_x4(b[bn], bRel[bn] + cx);
            #pragma unroll
            for (int mf = 0; mf < 2; mf++) {
                #pragma unroll
                for (int bn = 0; bn < 4; bn++) {
                    mma16816(acc[mf][bn * 2],     a[mf], b[bn][0], b[bn][2]);
                    mma16816(acc[mf][bn * 2 + 1], a[mf], b[bn][1], b[bn][3]);
                }
            }
        }

        __syncthreads();   // all A/B smem reads complete; s_p visible

        // issue next pair's loads NOW — they fly under the epilogue
        const int pn = *s_p;
        int ni = 0, nj = 0;
        if (pn < NPAIRS) {
            decode_pair(pn, ni, nj);
            issue_pair_loads(sb, tid, ni, nj, mbuf ^ 1);
        }

        // ---- epilogue: dual mining, direct fire-and-forget REDG to global ----
        unsigned* gHPi = g_hp + i * BM;
        unsigned* gHNi = g_hn + i * BM;
        unsigned* gHPj = g_hp + j * BM;
        unsigned* gHNj = g_hn + j * BM;
        const bool offdiag = (i != j);

        float hp[4], hn[4];
        #pragma unroll
        for (int e = 0; e < 4; e++) { hp[e] = 0.f; hn[e] = __int_as_float(0x7f800000); }

        #pragma unroll
        for (int nf = 0; nf < 8; nf++) {
            const int cb = warpN * 64 + nf * 8 + (lane & 3) * 2;
            const float2 mv0 = mB[cb], mv1 = mB[cb + 1];
            const int lb0 = __float_as_int(mv0.x), lb1 = __float_as_int(mv1.x);
            float cp0 = 0.f, cp1 = 0.f;
            float cn0 = __int_as_float(0x7f800000), cn1 = cn0;
            #pragma unroll
            for (int mf = 0; mf < 2; mf++) {
                const int rlo = mf * 2, rhi = mf * 2 + 1;
                float d00 = fmaf(-2.f, acc[mf][nf][0], sqa[rlo] + mv0.y);
                float d01 = fmaf(-2.f, acc[mf][nf][1], sqa[rlo] + mv1.y);
                float d10 = fmaf(-2.f, acc[mf][nf][2], sqa[rhi] + mv0.y);
                float d11 = fmaf(-2.f, acc[mf][nf][3], sqa[rhi] + mv1.y);
                if (lb0 == labA[rlo]) { hp[rlo] = fmaxf(hp[rlo], d00); cp0 = fmaxf(cp0, d00); }
                else                  { hn[rlo] = fminf(hn[rlo], d00); cn0 = fminf(cn0, d00); }
                if (lb1 == labA[rlo]) { hp[rlo] = fmaxf(hp[rlo], d01); cp1 = fmaxf(cp1, d01); }
                else                  { hn[rlo] = fminf(hn[rlo], d01); cn1 = fminf(cn1, d01); }
                if (lb0 == labA[rhi]) { hp[rhi] = fmaxf(hp[rhi], d10); cp0 = fmaxf(cp0, d10); }
                else                  { hn[rhi] = fminf(hn[rhi], d10); cn0 = fminf(cn0, d10); }
                if (lb1 == labA[rhi]) { hp[rhi] = fmaxf(hp[rhi], d11); cp1 = fmaxf(cp1, d11); }
                else                  { hn[rhi] = fminf(hn[rhi], d11); cn1 = fminf(cn1, d11); }
            }
            if (offdiag) {
                #pragma unroll
                for (int o = 4; o <= 16; o <<= 1) {
                    cp0 = fmaxf(cp0, __shfl_xor_sync(0xffffffffu, cp0, o));
                    cp1 = fmaxf(cp1, __shfl_xor_sync(0xffffffffu, cp1, o));
                    cn0 = fminf(cn0, __shfl_xor_sync(0xffffffffu, cn0, o));
                    cn1 = fminf(cn1, __shfl_xor_sync(0xffffffffu, cn1, o));
                }
                if (lane < 4) {
                    const int cc = warpN * 64 + nf * 8 + lane * 2;
                    atomicMax(&gHPj[cc],     __float_as_uint(cp0));
                    atomicMin(&gHNj[cc],     __float_as_uint(cn0));
                    atomicMax(&gHPj[cc + 1], __float_as_uint(cp1));
                    atomicMin(&gHNj[cc + 1], __float_as_uint(cn1));
                }
            }
        }
        #pragma unroll
        for (int e = 0; e < 4; e++) {
            hp[e] = fmaxf(hp[e], __shfl_xor_sync(0xffffffffu, hp[e], 1));
            hp[e] = fmaxf(hp[e], __shfl_xor_sync(0xffffffffu, hp[e], 2));
            hn[e] = fminf(hn[e], __shfl_xor_sync(0xffffffffu, hn[e], 1));
            hn[e] = fminf(hn[e], __shfl_xor_sync(0xffffffffu, hn[e], 2));
        }
        if ((lane & 3) == 0) {
            #pragma unroll
            for (int e = 0; e < 4; e++) {
                int r = warpM * 32 + (e >> 1) * 16 + (e & 1) * 8 + (lane >> 2);
                atomicMax(&gHPi[r], __float_as_uint(hp[e]));
                atomicMin(&gHNi[r], __float_as_uint(hn[e]));
            }
        }

        p = pn; i = ni; j = nj; mbuf ^= 1;
    }
}

// ---------------- finalize: 64 blocks, deterministic fixed-point accumulation ----------------
__global__ void finalize_kernel(float* __restrict__ out) {
    __shared__ float red[4];
    const int tid = threadIdx.x, wid = tid >> 5, lane = tid & 31;
    const int r = blockIdx.x * 128 + tid;
    float hp = sqrtf(__uint_as_float(g_hp[r]));
    float hn = sqrtf(__uint_as_float(g_hn[r]));    // +inf -> loss 0
    float s = fmaxf(hp - hn + MARGIN, 0.f);
    #pragma unroll
    for (int o = 16; o; o >>= 1) s += __shfl_xor_sync(0xffffffffu, s, o);
    if (lane == 0) red[wid] = s;
    __syncthreads();
    if (tid == 0) {
        float bs = red[0] + red[1] + red[2] + red[3];
        unsigned long long qv = (unsigned long long)__float2ll_rn(bs * 16777216.0f);
        atomicAdd(&g_isum, qv);
        __threadfence();
        unsigned done = atomicAdd(&g_done, 1u);
        if (done == 63u) {
            unsigned long long v = atomicAdd(&g_isum, 0ull);
            out[0] = (float)((double)v * (1.0 / (16777216.0 * 8192.0)));
        }
    }
}

extern "C" void kernel_launch(void* const* d_in, const int* in_sizes, int n_in,
                              void* d_out, int out_size) {
    const float* X   = (const float*)d_in[0];
    const int* lab32 = (const int*)d_in[1];
    float* out = (float*)d_out;

    cudaFuncSetAttribute(mma_kernel, cudaFuncAttributeMaxDynamicSharedMemorySize, SM_TOT);

    prep_kernel<<<NROWS / 32, 256>>>(X, lab32);
    mma_kernel<<<GRID_MMA, 256, SM_TOT>>>();
    finalize_kernel<<<64, 128>>>(out);
}